// round 4
// baseline (speedup 1.0000x reference)
#include <cuda_runtime.h>
#include <math.h>
#include <stdint.h>

#define T_LEN  2048
#define IN_DIM 1024
#define H_DIM  1024
#define FH     4096
#define C_DIM  1000
#define NCTA_DIR 64
#define SCAN_SMEM ((32*1024 + 1024) * 4)

// ---------------- device scratch (no allocations allowed) ----------------
__device__ __align__(16) float g_xp[2][T_LEN][FH];      // input projections (fwd, bwd-reversed order)
__device__ __align__(16) float g_hs[2][T_LEN][H_DIM];   // all hidden states (bwd stored in reversed time)
// tagged h ring: depth 2, each entry packs {h_bits, tag} in one 8B word.
// tag for input-to-step-s is s+1 (init h0 -> tag 1 in slot 0). step s writes slot (s+1)&1 with tag s+2.
__device__ __align__(16) uint64_t g_hpack[2][2][H_DIM];

__device__ __forceinline__ float to_tf32(float x) {
    uint32_t u;
    asm("cvt.rna.tf32.f32 %0, %1;" : "=r"(u) : "f"(x));
    return __uint_as_float(u);
}

__device__ __forceinline__ void mma_tf32(float* c, const uint32_t* a, const uint32_t* b) {
    asm volatile(
        "mma.sync.aligned.m16n8k8.row.col.f32.tf32.tf32.f32 "
        "{%0,%1,%2,%3}, {%4,%5,%6,%7}, {%8,%9}, {%0,%1,%2,%3};\n"
        : "+f"(c[0]), "+f"(c[1]), "+f"(c[2]), "+f"(c[3])
        : "r"(a[0]), "r"(a[1]), "r"(a[2]), "r"(a[3]), "r"(b[0]), "r"(b[1]));
}

__device__ __forceinline__ int swz(int r, int c) {
    return r * 32 + ((((c >> 2) ^ (r & 7)) << 2) | (c & 3));
}

// ---------------- init: reset h ring tags every launch/replay ----------------
__global__ void init_kernel() {
    int tid = blockIdx.x * blockDim.x + threadIdx.x;   // 0..4095
    if (tid < 2 * 2 * H_DIM) {
        int slot = (tid >> 10) & 1;
        // slot 0: h=0, tag=1 (input to step 0). slot 1: tag=0 (invalid until step 0 writes).
        ((uint64_t*)g_hpack)[tid] = slot == 0 ? ((uint64_t)1 << 32) : 0ull;
    }
}

// ---------------- phase 1: x @ W_ih^T + b_ih + b_hh via TF32 tensor cores ----------------
__global__ __launch_bounds__(256, 1) void xproj_mma(
    const float* __restrict__ x,
    const float* __restrict__ Wf, const float* __restrict__ Wb,
    const float* __restrict__ bif, const float* __restrict__ bhf,
    const float* __restrict__ bib, const float* __restrict__ bhb)
{
    const int dir = blockIdx.z;
    const float* __restrict__ W  = dir ? Wb  : Wf;
    const float* __restrict__ b1 = dir ? bib : bif;
    const float* __restrict__ b2 = dir ? bhb : bhf;

    __shared__ float sA[128 * 32];
    __shared__ float sB[128 * 32];

    const int tid = threadIdx.x;
    const int warp = tid >> 5, l = tid & 31;
    const int wm = warp >> 1, wn = warp & 1;
    const int g = l >> 2, t = l & 3;
    const int m0 = blockIdx.y * 128, n0 = blockIdx.x * 128;

    const int sr  = tid >> 3;
    const int sc4 = tid & 7;
    const int scs = ((sc4 ^ (sr & 7)) << 2);

    float acc[2][8][4];
    #pragma unroll
    for (int mi = 0; mi < 2; ++mi)
        #pragma unroll
        for (int ni = 0; ni < 8; ++ni)
            #pragma unroll
            for (int e = 0; e < 4; ++e) acc[mi][ni][e] = 0.f;

    float4 pa[4], pb[4];
    {
        const int kc = sc4 * 4;
        #pragma unroll
        for (int p = 0; p < 4; ++p) {
            int m = m0 + sr + 32 * p;
            int ar = dir ? (T_LEN - 1 - m) : m;
            pa[p] = *(const float4*)(x + (size_t)ar * IN_DIM + kc);
            pb[p] = *(const float4*)(W + (size_t)(n0 + sr + 32 * p) * IN_DIM + kc);
        }
        #pragma unroll
        for (int p = 0; p < 4; ++p) {
            int r = sr + 32 * p;
            float* da = &sA[r * 32 + scs];
            float* db = &sB[r * 32 + scs];
            da[0] = to_tf32(pa[p].x); da[1] = to_tf32(pa[p].y); da[2] = to_tf32(pa[p].z); da[3] = to_tf32(pa[p].w);
            db[0] = to_tf32(pb[p].x); db[1] = to_tf32(pb[p].y); db[2] = to_tf32(pb[p].z); db[3] = to_tf32(pb[p].w);
        }
    }
    __syncthreads();

    for (int kt = 0; kt < IN_DIM / 32; ++kt) {
        if (kt < IN_DIM / 32 - 1) {
            const int kc = (kt + 1) * 32 + sc4 * 4;
            #pragma unroll
            for (int p = 0; p < 4; ++p) {
                int m = m0 + sr + 32 * p;
                int ar = dir ? (T_LEN - 1 - m) : m;
                pa[p] = *(const float4*)(x + (size_t)ar * IN_DIM + kc);
                pb[p] = *(const float4*)(W + (size_t)(n0 + sr + 32 * p) * IN_DIM + kc);
            }
        }
        #pragma unroll
        for (int k8 = 0; k8 < 4; ++k8) {
            const int kk = k8 * 8;
            uint32_t a[2][4], b[8][2];
            #pragma unroll
            for (int mi = 0; mi < 2; ++mi) {
                int r = wm * 32 + mi * 16 + g;
                a[mi][0] = __float_as_uint(sA[swz(r,     kk + t)]);
                a[mi][1] = __float_as_uint(sA[swz(r + 8, kk + t)]);
                a[mi][2] = __float_as_uint(sA[swz(r,     kk + t + 4)]);
                a[mi][3] = __float_as_uint(sA[swz(r + 8, kk + t + 4)]);
            }
            #pragma unroll
            for (int ni = 0; ni < 8; ++ni) {
                int rn = wn * 64 + ni * 8 + g;
                b[ni][0] = __float_as_uint(sB[swz(rn, kk + t)]);
                b[ni][1] = __float_as_uint(sB[swz(rn, kk + t + 4)]);
            }
            #pragma unroll
            for (int mi = 0; mi < 2; ++mi)
                #pragma unroll
                for (int ni = 0; ni < 8; ++ni)
                    mma_tf32(acc[mi][ni], a[mi], b[ni]);
        }
        __syncthreads();
        if (kt < IN_DIM / 32 - 1) {
            #pragma unroll
            for (int p = 0; p < 4; ++p) {
                int r = sr + 32 * p;
                float* da = &sA[r * 32 + scs];
                float* db = &sB[r * 32 + scs];
                da[0] = to_tf32(pa[p].x); da[1] = to_tf32(pa[p].y); da[2] = to_tf32(pa[p].z); da[3] = to_tf32(pa[p].w);
                db[0] = to_tf32(pb[p].x); db[1] = to_tf32(pb[p].y); db[2] = to_tf32(pb[p].z); db[3] = to_tf32(pb[p].w);
            }
            __syncthreads();
        }
    }

    #pragma unroll
    for (int mi = 0; mi < 2; ++mi) {
        int r0 = m0 + wm * 32 + mi * 16 + g;
        #pragma unroll
        for (int ni = 0; ni < 8; ++ni) {
            int n = n0 + wn * 64 + ni * 8 + 2 * t;
            float bb0 = __ldg(b1 + n)     + __ldg(b2 + n);
            float bb1 = __ldg(b1 + n + 1) + __ldg(b2 + n + 1);
            float2 v0 = make_float2(acc[mi][ni][0] + bb0, acc[mi][ni][1] + bb1);
            float2 v1 = make_float2(acc[mi][ni][2] + bb0, acc[mi][ni][3] + bb1);
            *(float2*)&g_xp[dir][r0][n]     = v0;
            *(float2*)&g_xp[dir][r0 + 8][n] = v1;
        }
    }
}

// ---------------- phase 2: persistent LSTM scan, barrier-free tagged dataflow ----------------
// 128 CTAs (blockIdx>>6 = direction, &63 = chunk). 256 threads = 8 warps.
// Each warp owns 2 hidden units: unit A weights in registers, unit B in SMEM.
// Handoff: each unit's h published as one relaxed 8B {h,tag} store; consumers poll
// with predicated relaxed loads + nanosleep backoff. No fences, no barriers, no atomics.
__global__ __launch_bounds__(256, 1) void scan_kernel(
    const float* __restrict__ Whh_f, const float* __restrict__ Whh_b)
{
    extern __shared__ float smem[];
    float* sW = smem;             // 32 rows x 1024 (unit-B weights)
    float* sH = smem + 32*1024;   // 1024 (staged h)

    const int dir = blockIdx.x >> 6;
    const int cb  = blockIdx.x & 63;
    const float* __restrict__ Whh = dir ? Whh_b : Whh_f;

    const int tid = threadIdx.x;
    const int w = tid >> 5;
    const int l = tid & 31;
    const int uA = cb*16 + w;        // register unit
    const int uB = cb*16 + 8 + w;    // smem unit

    for (int i = tid; i < 32*1024/4; i += 256) {
        int rr = i >> 8;
        int col4 = i & 255;
        int lw = rr >> 2;
        int g  = rr & 3;
        int uu = cb*16 + 8 + lw;
        ((float4*)sW)[i] = __ldg((const float4*)(Whh + (size_t)(g*H_DIM + uu)*H_DIM) + col4);
    }

    float4 wr[4][8];
    #pragma unroll
    for (int g = 0; g < 4; ++g) {
        const float4* base = (const float4*)(Whh + (size_t)(g*H_DIM + uA)*H_DIM);
        #pragma unroll
        for (int jj = 0; jj < 8; ++jj)
            wr[g][jj] = __ldg(base + (l + 32*jj));
    }
    __syncthreads();

    float cA = 0.f, cB = 0.f;
    const float* xp = &g_xp[dir][0][0];
    float* hs = &g_hs[dir][0][0];
    const int xrow = (l & 3)*H_DIM + ((l < 4) ? uA : uB);

    for (int step = 0; step < T_LEN; ++step) {
        // issue xp gmem load first so its latency hides under polling
        float xpv = (l < 8) ? __ldg(xp + (size_t)step*FH + xrow) : 0.f;

        // poll 4 units of h (tagged, relaxed 8B atomic loads)
        const uint64_t* src = &g_hpack[dir][step & 1][tid * 4];
        const uint32_t expect = (uint32_t)(step + 1);
        float v0, v1, v2, v3;
        {
            unsigned miss = 0xFu;
            do {
                uint64_t p;
                if (miss & 1u) { asm volatile("ld.relaxed.gpu.global.b64 %0,[%1];" : "=l"(p) : "l"(src+0) : "memory");
                                 if ((uint32_t)(p >> 32) == expect) { v0 = __uint_as_float((uint32_t)p); miss &= ~1u; } }
                if (miss & 2u) { asm volatile("ld.relaxed.gpu.global.b64 %0,[%1];" : "=l"(p) : "l"(src+1) : "memory");
                                 if ((uint32_t)(p >> 32) == expect) { v1 = __uint_as_float((uint32_t)p); miss &= ~2u; } }
                if (miss & 4u) { asm volatile("ld.relaxed.gpu.global.b64 %0,[%1];" : "=l"(p) : "l"(src+2) : "memory");
                                 if ((uint32_t)(p >> 32) == expect) { v2 = __uint_as_float((uint32_t)p); miss &= ~4u; } }
                if (miss & 8u) { asm volatile("ld.relaxed.gpu.global.b64 %0,[%1];" : "=l"(p) : "l"(src+3) : "memory");
                                 if ((uint32_t)(p >> 32) == expect) { v3 = __uint_as_float((uint32_t)p); miss &= ~8u; } }
                if (miss) __nanosleep(32);
            } while (miss);
        }
        ((float4*)sH)[tid] = make_float4(v0, v1, v2, v3);
        __syncthreads();

        float acc[8];
        #pragma unroll
        for (int g = 0; g < 8; ++g) acc[g] = 0.f;

        const float4* sH4 = (const float4*)sH;
        const float4* sW4 = (const float4*)sW;
        #pragma unroll
        for (int jj = 0; jj < 8; ++jj) {
            float4 h4 = sH4[l + 32*jj];
            #pragma unroll
            for (int g = 0; g < 4; ++g) {
                float4 a = wr[g][jj];
                acc[g]   = fmaf(a.x,h4.x, fmaf(a.y,h4.y, fmaf(a.z,h4.z, fmaf(a.w,h4.w, acc[g]))));
                float4 b = sW4[(w*4 + g)*256 + l + 32*jj];
                acc[4+g] = fmaf(b.x,h4.x, fmaf(b.y,h4.y, fmaf(b.z,h4.z, fmaf(b.w,h4.w, acc[4+g]))));
            }
        }

        #pragma unroll
        for (int off = 16; off; off >>= 1)
            #pragma unroll
            for (int g = 0; g < 8; ++g)
                acc[g] += __shfl_xor_sync(0xffffffffu, acc[g], off);

        float s01 = (l & 1) ? acc[1] : acc[0];
        float s23 = (l & 1) ? acc[3] : acc[2];
        float s45 = (l & 1) ? acc[5] : acc[4];
        float s67 = (l & 1) ? acc[7] : acc[6];
        float sab = (l & 2) ? s23 : s01;
        float scd = (l & 2) ? s67 : s45;
        float pre = ((l & 4) ? scd : sab) + xpv;
        float act;
        if ((l & 3) == 2) act = tanhf(pre);
        else              act = 1.f / (1.f + expf(-pre));

        float iA = __shfl_sync(0xffffffffu, act, 0);
        float fA = __shfl_sync(0xffffffffu, act, 1);
        float gA = __shfl_sync(0xffffffffu, act, 2);
        float oA = __shfl_sync(0xffffffffu, act, 3);
        float iB = __shfl_sync(0xffffffffu, act, 4);
        float fB = __shfl_sync(0xffffffffu, act, 5);
        float gB = __shfl_sync(0xffffffffu, act, 6);
        float oB = __shfl_sync(0xffffffffu, act, 7);

        cA = fmaf(fA, cA, iA * gA);
        cB = fmaf(fB, cB, iB * gB);
        float hA = oA * tanhf(cA);
        float hB = oB * tanhf(cB);

        // publish {h, step+2} for next step; also record history for fc phase
        const uint64_t tagbits = (uint64_t)(uint32_t)(step + 2) << 32;
        if (l == 0) {
            uint64_t p = tagbits | (uint64_t)__float_as_uint(hA);
            asm volatile("st.relaxed.gpu.global.b64 [%0],%1;" :: "l"(&g_hpack[dir][(step+1)&1][uA]), "l"(p) : "memory");
            hs[(size_t)step*H_DIM + uA] = hA;
        }
        if (l == 1) {
            uint64_t p = tagbits | (uint64_t)__float_as_uint(hB);
            asm volatile("st.relaxed.gpu.global.b64 [%0],%1;" :: "l"(&g_hpack[dir][(step+1)&1][uB]), "l"(p) : "memory");
            hs[(size_t)step*H_DIM + uB] = hB;
        }
        __syncthreads();   // all warps done reading sH before next overwrite
    }
}

// ---------------- phase 3: out = concat(h_fwd, h_bwd) @ fc_W^T + fc_b via TF32 MMA ----------------
__global__ __launch_bounds__(256, 1) void fc_mma(
    const float* __restrict__ fcW, const float* __restrict__ fcb,
    float* __restrict__ out)
{
    __shared__ float sA[128 * 32];
    __shared__ float sB[128 * 32];

    const int tid = threadIdx.x;
    const int warp = tid >> 5, l = tid & 31;
    const int wm = warp >> 1, wn = warp & 1;
    const int g = l >> 2, t = l & 3;
    const int m0 = blockIdx.y * 128, n0 = blockIdx.x * 128;

    const int sr  = tid >> 3;
    const int sc4 = tid & 7;
    const int scs = ((sc4 ^ (sr & 7)) << 2);

    float acc[2][8][4];
    #pragma unroll
    for (int mi = 0; mi < 2; ++mi)
        #pragma unroll
        for (int ni = 0; ni < 8; ++ni)
            #pragma unroll
            for (int e = 0; e < 4; ++e) acc[mi][ni][e] = 0.f;

    float4 pa[4], pb[4];
    {
        const int kc = sc4 * 4;
        #pragma unroll
        for (int p = 0; p < 4; ++p) {
            int m = m0 + sr + 32 * p;
            const float* asrc = (kc < H_DIM) ? &g_hs[0][m][kc]
                                             : &g_hs[1][T_LEN - 1 - m][kc - H_DIM];
            pa[p] = *(const float4*)asrc;
            int n = n0 + sr + 32 * p;
            pb[p] = (n < C_DIM) ? *(const float4*)(fcW + (size_t)n * (2 * H_DIM) + kc)
                                : make_float4(0.f, 0.f, 0.f, 0.f);
        }
        #pragma unroll
        for (int p = 0; p < 4; ++p) {
            int r = sr + 32 * p;
            float* da = &sA[r * 32 + scs];
            float* db = &sB[r * 32 + scs];
            da[0] = to_tf32(pa[p].x); da[1] = to_tf32(pa[p].y); da[2] = to_tf32(pa[p].z); da[3] = to_tf32(pa[p].w);
            db[0] = to_tf32(pb[p].x); db[1] = to_tf32(pb[p].y); db[2] = to_tf32(pb[p].z); db[3] = to_tf32(pb[p].w);
        }
    }
    __syncthreads();

    const int KTOT = 2 * H_DIM;
    for (int kt = 0; kt < KTOT / 32; ++kt) {
        if (kt < KTOT / 32 - 1) {
            const int kc = (kt + 1) * 32 + sc4 * 4;
            #pragma unroll
            for (int p = 0; p < 4; ++p) {
                int m = m0 + sr + 32 * p;
                const float* asrc = (kc < H_DIM) ? &g_hs[0][m][kc]
                                                 : &g_hs[1][T_LEN - 1 - m][kc - H_DIM];
                pa[p] = *(const float4*)asrc;
                int n = n0 + sr + 32 * p;
                pb[p] = (n < C_DIM) ? *(const float4*)(fcW + (size_t)n * (2 * H_DIM) + kc)
                                    : make_float4(0.f, 0.f, 0.f, 0.f);
            }
        }
        #pragma unroll
        for (int k8 = 0; k8 < 4; ++k8) {
            const int kk = k8 * 8;
            uint32_t a[2][4], b[8][2];
            #pragma unroll
            for (int mi = 0; mi < 2; ++mi) {
                int r = wm * 32 + mi * 16 + g;
                a[mi][0] = __float_as_uint(sA[swz(r,     kk + t)]);
                a[mi][1] = __float_as_uint(sA[swz(r + 8, kk + t)]);
                a[mi][2] = __float_as_uint(sA[swz(r,     kk + t + 4)]);
                a[mi][3] = __float_as_uint(sA[swz(r + 8, kk + t + 4)]);
            }
            #pragma unroll
            for (int ni = 0; ni < 8; ++ni) {
                int rn = wn * 64 + ni * 8 + g;
                b[ni][0] = __float_as_uint(sB[swz(rn, kk + t)]);
                b[ni][1] = __float_as_uint(sB[swz(rn, kk + t + 4)]);
            }
            #pragma unroll
            for (int mi = 0; mi < 2; ++mi)
                #pragma unroll
                for (int ni = 0; ni < 8; ++ni)
                    mma_tf32(acc[mi][ni], a[mi], b[ni]);
        }
        __syncthreads();
        if (kt < KTOT / 32 - 1) {
            #pragma unroll
            for (int p = 0; p < 4; ++p) {
                int r = sr + 32 * p;
                float* da = &sA[r * 32 + scs];
                float* db = &sB[r * 32 + scs];
                da[0] = to_tf32(pa[p].x); da[1] = to_tf32(pa[p].y); da[2] = to_tf32(pa[p].z); da[3] = to_tf32(pa[p].w);
                db[0] = to_tf32(pb[p].x); db[1] = to_tf32(pb[p].y); db[2] = to_tf32(pb[p].z); db[3] = to_tf32(pb[p].w);
            }
            __syncthreads();
        }
    }

    #pragma unroll
    for (int mi = 0; mi < 2; ++mi) {
        int r0 = m0 + wm * 32 + mi * 16 + g;
        #pragma unroll
        for (int ni = 0; ni < 8; ++ni) {
            int n = n0 + wn * 64 + ni * 8 + 2 * t;
            if (n < C_DIM) {
                float bb0 = __ldg(fcb + n);
                float bb1 = __ldg(fcb + n + 1);
                float2 v0 = make_float2(acc[mi][ni][0] + bb0, acc[mi][ni][1] + bb1);
                float2 v1 = make_float2(acc[mi][ni][2] + bb0, acc[mi][ni][3] + bb1);
                *(float2*)&out[(size_t)r0 * C_DIM + n]       = v0;
                *(float2*)&out[(size_t)(r0 + 8) * C_DIM + n] = v1;
            }
        }
    }
}

// ---------------- launch ----------------
extern "C" void kernel_launch(void* const* d_in, const int* in_sizes, int n_in,
                              void* d_out, int out_size)
{
    const float* x      = (const float*)d_in[0];
    const float* W_ih_f = (const float*)d_in[1];
    const float* W_hh_f = (const float*)d_in[2];
    const float* b_ih_f = (const float*)d_in[3];
    const float* b_hh_f = (const float*)d_in[4];
    const float* W_ih_b = (const float*)d_in[5];
    const float* W_hh_b = (const float*)d_in[6];
    const float* b_ih_b = (const float*)d_in[7];
    const float* b_hh_b = (const float*)d_in[8];
    const float* fc_W   = (const float*)d_in[9];
    const float* fc_b   = (const float*)d_in[10];
    float* out = (float*)d_out;

    cudaFuncSetAttribute(scan_kernel, cudaFuncAttributeMaxDynamicSharedMemorySize, SCAN_SMEM);

    init_kernel<<<16, 256>>>();
    xproj_mma<<<dim3(FH/128, T_LEN/128, 2), 256>>>(x, W_ih_f, W_ih_b,
                                                   b_ih_f, b_hh_f, b_ih_b, b_hh_b);
    scan_kernel<<<2*NCTA_DIR, 256, SCAN_SMEM>>>(W_hh_f, W_hh_b);
    fc_mma<<<dim3(8, T_LEN/128), 256>>>(fc_W, fc_b, out);
}

// round 5
// speedup vs baseline: 1.2968x; 1.2968x over previous
#include <cuda_runtime.h>
#include <math.h>
#include <stdint.h>

#define T_LEN  2048
#define IN_DIM 1024
#define H_DIM  1024
#define FH     4096
#define C_DIM  1000
#define NCTA_DIR 64
#define SCAN_SMEM ((32*1024 + 1024) * 4)

// ---------------- device scratch (no allocations allowed) ----------------
__device__ __align__(16) float g_xp[2][T_LEN][FH];      // input projections (fwd, bwd-reversed order)
__device__ __align__(16) float g_hs[2][T_LEN][H_DIM];   // all hidden states (bwd stored in reversed time)
__device__ __align__(16) float g_hbuf[2][2][H_DIM];     // double-buffered h per direction
// per-CTA progress flags, padded to 256B so consecutive flags land on distinct LTS slices
__device__ __align__(256) unsigned g_flag[2][NCTA_DIR][64];

__device__ __forceinline__ void st_release_u32(unsigned* p, unsigned v) {
    asm volatile("st.release.gpu.global.u32 [%0],%1;" :: "l"(p), "r"(v) : "memory");
}
__device__ __forceinline__ unsigned ld_acquire_u32(const unsigned* p) {
    unsigned v;
    asm volatile("ld.acquire.gpu.global.u32 %0,[%1];" : "=r"(v) : "l"(p) : "memory");
    return v;
}

__device__ __forceinline__ float to_tf32(float x) {
    uint32_t u;
    asm("cvt.rna.tf32.f32 %0, %1;" : "=r"(u) : "f"(x));
    return __uint_as_float(u);
}

__device__ __forceinline__ void mma_tf32(float* c, const uint32_t* a, const uint32_t* b) {
    asm volatile(
        "mma.sync.aligned.m16n8k8.row.col.f32.tf32.tf32.f32 "
        "{%0,%1,%2,%3}, {%4,%5,%6,%7}, {%8,%9}, {%0,%1,%2,%3};\n"
        : "+f"(c[0]), "+f"(c[1]), "+f"(c[2]), "+f"(c[3])
        : "r"(a[0]), "r"(a[1]), "r"(a[2]), "r"(a[3]), "r"(b[0]), "r"(b[1]));
}

__device__ __forceinline__ int swz(int r, int c) {
    return r * 32 + ((((c >> 2) ^ (r & 7)) << 2) | (c & 3));
}

// ---------------- init: reset flags + h0 every launch/replay ----------------
__global__ void init_kernel() {
    int tid = blockIdx.x * blockDim.x + threadIdx.x;
    if (tid < 2 * 2 * H_DIM) ((float*)g_hbuf)[tid] = 0.f;
    if (tid < 2 * NCTA_DIR * 64) ((unsigned*)g_flag)[tid] = 1u;   // h[0] ready
}

// ---------------- phase 1: x @ W_ih^T + b_ih + b_hh via TF32 tensor cores ----------------
__global__ __launch_bounds__(256, 1) void xproj_mma(
    const float* __restrict__ x,
    const float* __restrict__ Wf, const float* __restrict__ Wb,
    const float* __restrict__ bif, const float* __restrict__ bhf,
    const float* __restrict__ bib, const float* __restrict__ bhb)
{
    const int dir = blockIdx.z;
    const float* __restrict__ W  = dir ? Wb  : Wf;
    const float* __restrict__ b1 = dir ? bib : bif;
    const float* __restrict__ b2 = dir ? bhb : bhf;

    __shared__ float sA[128 * 32];
    __shared__ float sB[128 * 32];

    const int tid = threadIdx.x;
    const int warp = tid >> 5, l = tid & 31;
    const int wm = warp >> 1, wn = warp & 1;
    const int g = l >> 2, t = l & 3;
    const int m0 = blockIdx.y * 128, n0 = blockIdx.x * 128;

    const int sr  = tid >> 3;
    const int sc4 = tid & 7;
    const int scs = ((sc4 ^ (sr & 7)) << 2);

    float acc[2][8][4];
    #pragma unroll
    for (int mi = 0; mi < 2; ++mi)
        #pragma unroll
        for (int ni = 0; ni < 8; ++ni)
            #pragma unroll
            for (int e = 0; e < 4; ++e) acc[mi][ni][e] = 0.f;

    float4 pa[4], pb[4];
    {
        const int kc = sc4 * 4;
        #pragma unroll
        for (int p = 0; p < 4; ++p) {
            int m = m0 + sr + 32 * p;
            int ar = dir ? (T_LEN - 1 - m) : m;
            pa[p] = *(const float4*)(x + (size_t)ar * IN_DIM + kc);
            pb[p] = *(const float4*)(W + (size_t)(n0 + sr + 32 * p) * IN_DIM + kc);
        }
        #pragma unroll
        for (int p = 0; p < 4; ++p) {
            int r = sr + 32 * p;
            float* da = &sA[r * 32 + scs];
            float* db = &sB[r * 32 + scs];
            da[0] = to_tf32(pa[p].x); da[1] = to_tf32(pa[p].y); da[2] = to_tf32(pa[p].z); da[3] = to_tf32(pa[p].w);
            db[0] = to_tf32(pb[p].x); db[1] = to_tf32(pb[p].y); db[2] = to_tf32(pb[p].z); db[3] = to_tf32(pb[p].w);
        }
    }
    __syncthreads();

    for (int kt = 0; kt < IN_DIM / 32; ++kt) {
        if (kt < IN_DIM / 32 - 1) {
            const int kc = (kt + 1) * 32 + sc4 * 4;
            #pragma unroll
            for (int p = 0; p < 4; ++p) {
                int m = m0 + sr + 32 * p;
                int ar = dir ? (T_LEN - 1 - m) : m;
                pa[p] = *(const float4*)(x + (size_t)ar * IN_DIM + kc);
                pb[p] = *(const float4*)(W + (size_t)(n0 + sr + 32 * p) * IN_DIM + kc);
            }
        }
        #pragma unroll
        for (int k8 = 0; k8 < 4; ++k8) {
            const int kk = k8 * 8;
            uint32_t a[2][4], b[8][2];
            #pragma unroll
            for (int mi = 0; mi < 2; ++mi) {
                int r = wm * 32 + mi * 16 + g;
                a[mi][0] = __float_as_uint(sA[swz(r,     kk + t)]);
                a[mi][1] = __float_as_uint(sA[swz(r + 8, kk + t)]);
                a[mi][2] = __float_as_uint(sA[swz(r,     kk + t + 4)]);
                a[mi][3] = __float_as_uint(sA[swz(r + 8, kk + t + 4)]);
            }
            #pragma unroll
            for (int ni = 0; ni < 8; ++ni) {
                int rn = wn * 64 + ni * 8 + g;
                b[ni][0] = __float_as_uint(sB[swz(rn, kk + t)]);
                b[ni][1] = __float_as_uint(sB[swz(rn, kk + t + 4)]);
            }
            #pragma unroll
            for (int mi = 0; mi < 2; ++mi)
                #pragma unroll
                for (int ni = 0; ni < 8; ++ni)
                    mma_tf32(acc[mi][ni], a[mi], b[ni]);
        }
        __syncthreads();
        if (kt < IN_DIM / 32 - 1) {
            #pragma unroll
            for (int p = 0; p < 4; ++p) {
                int r = sr + 32 * p;
                float* da = &sA[r * 32 + scs];
                float* db = &sB[r * 32 + scs];
                da[0] = to_tf32(pa[p].x); da[1] = to_tf32(pa[p].y); da[2] = to_tf32(pa[p].z); da[3] = to_tf32(pa[p].w);
                db[0] = to_tf32(pb[p].x); db[1] = to_tf32(pb[p].y); db[2] = to_tf32(pb[p].z); db[3] = to_tf32(pb[p].w);
            }
            __syncthreads();
        }
    }

    #pragma unroll
    for (int mi = 0; mi < 2; ++mi) {
        int r0 = m0 + wm * 32 + mi * 16 + g;
        #pragma unroll
        for (int ni = 0; ni < 8; ++ni) {
            int n = n0 + wn * 64 + ni * 8 + 2 * t;
            float bb0 = __ldg(b1 + n)     + __ldg(b2 + n);
            float bb1 = __ldg(b1 + n + 1) + __ldg(b2 + n + 1);
            float2 v0 = make_float2(acc[mi][ni][0] + bb0, acc[mi][ni][1] + bb1);
            float2 v1 = make_float2(acc[mi][ni][2] + bb0, acc[mi][ni][3] + bb1);
            *(float2*)&g_xp[dir][r0][n]     = v0;
            *(float2*)&g_xp[dir][r0 + 8][n] = v1;
        }
    }
}

// ---------------- phase 2: persistent LSTM scan, per-CTA flag barrier ----------------
// 128 CTAs (blockIdx>>6 = direction, &63 = chunk). 256 threads = 8 warps.
// Warp owns 2 units: unit A weights in registers, unit B in SMEM.
// Handoff: h via __stcg/__ldcg double buffer; release via ONE st.release per CTA to a
// private padded flag; consumers poll 64 flags with warp 0 (read-only, no RMW anywhere).
__global__ __launch_bounds__(256, 1) void scan_kernel(
    const float* __restrict__ Whh_f, const float* __restrict__ Whh_b)
{
    extern __shared__ float smem[];
    float* sW = smem;             // 32 rows x 1024 (unit-B weights)
    float* sH = smem + 32*1024;   // 1024 (staged h)

    const int dir = blockIdx.x >> 6;
    const int cb  = blockIdx.x & 63;
    const float* __restrict__ Whh = dir ? Whh_b : Whh_f;

    const int tid = threadIdx.x;
    const int w = tid >> 5;
    const int l = tid & 31;
    const int uA = cb*16 + w;        // register unit
    const int uB = cb*16 + 8 + w;    // smem unit

    for (int i = tid; i < 32*1024/4; i += 256) {
        int rr = i >> 8;
        int col4 = i & 255;
        int lw = rr >> 2;
        int g  = rr & 3;
        int uu = cb*16 + 8 + lw;
        ((float4*)sW)[i] = __ldg((const float4*)(Whh + (size_t)(g*H_DIM + uu)*H_DIM) + col4);
    }

    float4 wr[4][8];
    #pragma unroll
    for (int g = 0; g < 4; ++g) {
        const float4* base = (const float4*)(Whh + (size_t)(g*H_DIM + uA)*H_DIM);
        #pragma unroll
        for (int jj = 0; jj < 8; ++jj)
            wr[g][jj] = __ldg(base + (l + 32*jj));
    }
    __syncthreads();

    float cA = 0.f, cB = 0.f;
    const float* xp = &g_xp[dir][0][0];
    float* hs = &g_hs[dir][0][0];
    // all lanes in a quad load the same xp element: gate=(l>>2)&3, unit A for l<16 else B
    const int xrow = (((l >> 2) & 3))*H_DIM + ((l & 16) ? uB : uA);

    for (int step = 0; step < T_LEN; ++step) {
        // independent gmem load issued early to overlap with flag polling
        float xpv = __ldg(xp + (size_t)step*FH + xrow);

        // warp 0: poll all 64 producer flags (2 per lane), read-only acquire loads
        if (w == 0) {
            const unsigned expect = (unsigned)(step + 1);
            const unsigned* f0 = &g_flag[dir][l][0];
            const unsigned* f1 = &g_flag[dir][l + 32][0];
            bool d0 = false, d1 = false;
            for (;;) {
                if (!d0) d0 = ld_acquire_u32(f0) >= expect;
                if (!d1) d1 = ld_acquire_u32(f1) >= expect;
                if (__all_sync(0xffffffffu, d0 && d1)) break;
            }
        }
        __syncthreads();

        // stage h[step] into smem (L2-direct; L1 may be stale)
        float4 hv = __ldcg((const float4*)&g_hbuf[dir][step & 1][0] + tid);
        ((float4*)sH)[tid] = hv;
        __syncthreads();

        float acc[8];
        #pragma unroll
        for (int g = 0; g < 8; ++g) acc[g] = 0.f;

        const float4* sH4 = (const float4*)sH;
        const float4* sW4 = (const float4*)sW;
        #pragma unroll
        for (int jj = 0; jj < 8; ++jj) {
            float4 h4 = sH4[l + 32*jj];
            #pragma unroll
            for (int g = 0; g < 4; ++g) {
                float4 a = wr[g][jj];
                acc[g]   = fmaf(a.x,h4.x, fmaf(a.y,h4.y, fmaf(a.z,h4.z, fmaf(a.w,h4.w, acc[g]))));
                float4 b = sW4[(w*4 + g)*256 + l + 32*jj];
                acc[4+g] = fmaf(b.x,h4.x, fmaf(b.y,h4.y, fmaf(b.z,h4.z, fmaf(b.w,h4.w, acc[4+g]))));
            }
        }

        // value-merging butterfly: 16 shfls instead of 40
        #pragma unroll
        for (int g = 0; g < 8; ++g) acc[g] += __shfl_xor_sync(0xffffffffu, acc[g], 16);
        float v0 = (l & 16) ? acc[4] : acc[0];
        float v1 = (l & 16) ? acc[5] : acc[1];
        float v2 = (l & 16) ? acc[6] : acc[2];
        float v3 = (l & 16) ? acc[7] : acc[3];
        v0 += __shfl_xor_sync(0xffffffffu, v0, 8);
        v1 += __shfl_xor_sync(0xffffffffu, v1, 8);
        v2 += __shfl_xor_sync(0xffffffffu, v2, 8);
        v3 += __shfl_xor_sync(0xffffffffu, v3, 8);
        float u0 = (l & 8) ? v2 : v0;
        float u1 = (l & 8) ? v3 : v1;
        u0 += __shfl_xor_sync(0xffffffffu, u0, 4);
        u1 += __shfl_xor_sync(0xffffffffu, u1, 4);
        float t = (l & 4) ? u1 : u0;
        t += __shfl_xor_sync(0xffffffffu, t, 2);
        t += __shfl_xor_sync(0xffffffffu, t, 1);
        // lane l now holds gate sum for g(l) = 4*(l>>4) + ((l>>2)&3)

        float pre = t + xpv;
        float act;
        if (((l >> 2) & 3) == 2) {             // candidate gate: tanh
            float e = __expf(-2.f * fabsf(pre));
            act = copysignf((1.f - e) / (1.f + e), pre);
        } else {                               // i/f/o gates: sigmoid
            act = 1.f / (1.f + __expf(-pre));
        }

        float iA = __shfl_sync(0xffffffffu, act, 0);
        float fA = __shfl_sync(0xffffffffu, act, 4);
        float gA = __shfl_sync(0xffffffffu, act, 8);
        float oA = __shfl_sync(0xffffffffu, act, 12);
        float iB = __shfl_sync(0xffffffffu, act, 16);
        float fB = __shfl_sync(0xffffffffu, act, 20);
        float gB = __shfl_sync(0xffffffffu, act, 24);
        float oB = __shfl_sync(0xffffffffu, act, 28);

        cA = fmaf(fA, cA, iA * gA);
        cB = fmaf(fB, cB, iB * gB);
        float eA = __expf(-2.f * fabsf(cA));
        float eB = __expf(-2.f * fabsf(cB));
        float hA = oA * copysignf((1.f - eA) / (1.f + eA), cA);
        float hB = oB * copysignf((1.f - eB) / (1.f + eB), cB);

        float* hnext = &g_hbuf[dir][(step + 1) & 1][0];
        if (l == 0) { __stcg(&hnext[uA], hA); hs[(size_t)step*H_DIM + uA] = hA; }
        if (l == 4) { __stcg(&hnext[uB], hB); hs[(size_t)step*H_DIM + uB] = hB; }
        __syncthreads();                        // all h stores of this CTA issued before release
        if (tid == 0) st_release_u32(&g_flag[dir][cb][0], (unsigned)(step + 2));
    }
}

// ---------------- phase 3: out = concat(h_fwd, h_bwd) @ fc_W^T + fc_b via TF32 MMA ----------------
__global__ __launch_bounds__(256, 1) void fc_mma(
    const float* __restrict__ fcW, const float* __restrict__ fcb,
    float* __restrict__ out)
{
    __shared__ float sA[128 * 32];
    __shared__ float sB[128 * 32];

    const int tid = threadIdx.x;
    const int warp = tid >> 5, l = tid & 31;
    const int wm = warp >> 1, wn = warp & 1;
    const int g = l >> 2, t = l & 3;
    const int m0 = blockIdx.y * 128, n0 = blockIdx.x * 128;

    const int sr  = tid >> 3;
    const int sc4 = tid & 7;
    const int scs = ((sc4 ^ (sr & 7)) << 2);

    float acc[2][8][4];
    #pragma unroll
    for (int mi = 0; mi < 2; ++mi)
        #pragma unroll
        for (int ni = 0; ni < 8; ++ni)
            #pragma unroll
            for (int e = 0; e < 4; ++e) acc[mi][ni][e] = 0.f;

    float4 pa[4], pb[4];
    {
        const int kc = sc4 * 4;
        #pragma unroll
        for (int p = 0; p < 4; ++p) {
            int m = m0 + sr + 32 * p;
            const float* asrc = (kc < H_DIM) ? &g_hs[0][m][kc]
                                             : &g_hs[1][T_LEN - 1 - m][kc - H_DIM];
            pa[p] = *(const float4*)asrc;
            int n = n0 + sr + 32 * p;
            pb[p] = (n < C_DIM) ? *(const float4*)(fcW + (size_t)n * (2 * H_DIM) + kc)
                                : make_float4(0.f, 0.f, 0.f, 0.f);
        }
        #pragma unroll
        for (int p = 0; p < 4; ++p) {
            int r = sr + 32 * p;
            float* da = &sA[r * 32 + scs];
            float* db = &sB[r * 32 + scs];
            da[0] = to_tf32(pa[p].x); da[1] = to_tf32(pa[p].y); da[2] = to_tf32(pa[p].z); da[3] = to_tf32(pa[p].w);
            db[0] = to_tf32(pb[p].x); db[1] = to_tf32(pb[p].y); db[2] = to_tf32(pb[p].z); db[3] = to_tf32(pb[p].w);
        }
    }
    __syncthreads();

    const int KTOT = 2 * H_DIM;
    for (int kt = 0; kt < KTOT / 32; ++kt) {
        if (kt < KTOT / 32 - 1) {
            const int kc = (kt + 1) * 32 + sc4 * 4;
            #pragma unroll
            for (int p = 0; p < 4; ++p) {
                int m = m0 + sr + 32 * p;
                const float* asrc = (kc < H_DIM) ? &g_hs[0][m][kc]
                                                 : &g_hs[1][T_LEN - 1 - m][kc - H_DIM];
                pa[p] = *(const float4*)asrc;
                int n = n0 + sr + 32 * p;
                pb[p] = (n < C_DIM) ? *(const float4*)(fcW + (size_t)n * (2 * H_DIM) + kc)
                                    : make_float4(0.f, 0.f, 0.f, 0.f);
            }
        }
        #pragma unroll
        for (int k8 = 0; k8 < 4; ++k8) {
            const int kk = k8 * 8;
            uint32_t a[2][4], b[8][2];
            #pragma unroll
            for (int mi = 0; mi < 2; ++mi) {
                int r = wm * 32 + mi * 16 + g;
                a[mi][0] = __float_as_uint(sA[swz(r,     kk + t)]);
                a[mi][1] = __float_as_uint(sA[swz(r + 8, kk + t)]);
                a[mi][2] = __float_as_uint(sA[swz(r,     kk + t + 4)]);
                a[mi][3] = __float_as_uint(sA[swz(r + 8, kk + t + 4)]);
            }
            #pragma unroll
            for (int ni = 0; ni < 8; ++ni) {
                int rn = wn * 64 + ni * 8 + g;
                b[ni][0] = __float_as_uint(sB[swz(rn, kk + t)]);
                b[ni][1] = __float_as_uint(sB[swz(rn, kk + t + 4)]);
            }
            #pragma unroll
            for (int mi = 0; mi < 2; ++mi)
                #pragma unroll
                for (int ni = 0; ni < 8; ++ni)
                    mma_tf32(acc[mi][ni], a[mi], b[ni]);
        }
        __syncthreads();
        if (kt < KTOT / 32 - 1) {
            #pragma unroll
            for (int p = 0; p < 4; ++p) {
                int r = sr + 32 * p;
                float* da = &sA[r * 32 + scs];
                float* db = &sB[r * 32 + scs];
                da[0] = to_tf32(pa[p].x); da[1] = to_tf32(pa[p].y); da[2] = to_tf32(pa[p].z); da[3] = to_tf32(pa[p].w);
                db[0] = to_tf32(pb[p].x); db[1] = to_tf32(pb[p].y); db[2] = to_tf32(pb[p].z); db[3] = to_tf32(pb[p].w);
            }
            __syncthreads();
        }
    }

    #pragma unroll
    for (int mi = 0; mi < 2; ++mi) {
        int r0 = m0 + wm * 32 + mi * 16 + g;
        #pragma unroll
        for (int ni = 0; ni < 8; ++ni) {
            int n = n0 + wn * 64 + ni * 8 + 2 * t;
            if (n < C_DIM) {
                float bb0 = __ldg(fcb + n);
                float bb1 = __ldg(fcb + n + 1);
                float2 v0 = make_float2(acc[mi][ni][0] + bb0, acc[mi][ni][1] + bb1);
                float2 v1 = make_float2(acc[mi][ni][2] + bb0, acc[mi][ni][3] + bb1);
                *(float2*)&out[(size_t)r0 * C_DIM + n]       = v0;
                *(float2*)&out[(size_t)(r0 + 8) * C_DIM + n] = v1;
            }
        }
    }
}

// ---------------- launch ----------------
extern "C" void kernel_launch(void* const* d_in, const int* in_sizes, int n_in,
                              void* d_out, int out_size)
{
    const float* x      = (const float*)d_in[0];
    const float* W_ih_f = (const float*)d_in[1];
    const float* W_hh_f = (const float*)d_in[2];
    const float* b_ih_f = (const float*)d_in[3];
    const float* b_hh_f = (const float*)d_in[4];
    const float* W_ih_b = (const float*)d_in[5];
    const float* W_hh_b = (const float*)d_in[6];
    const float* b_ih_b = (const float*)d_in[7];
    const float* b_hh_b = (const float*)d_in[8];
    const float* fc_W   = (const float*)d_in[9];
    const float* fc_b   = (const float*)d_in[10];
    float* out = (float*)d_out;

    cudaFuncSetAttribute(scan_kernel, cudaFuncAttributeMaxDynamicSharedMemorySize, SCAN_SMEM);

    init_kernel<<<32, 256>>>();
    xproj_mma<<<dim3(FH/128, T_LEN/128, 2), 256>>>(x, W_ih_f, W_ih_b,
                                                   b_ih_f, b_hh_f, b_ih_b, b_hh_b);
    scan_kernel<<<2*NCTA_DIR, 256, SCAN_SMEM>>>(W_hh_f, W_hh_b);
    fc_mma<<<dim3(8, T_LEN/128), 256>>>(fc_W, fc_b, out);
}

// round 6
// speedup vs baseline: 1.4854x; 1.1454x over previous
#include <cuda_runtime.h>
#include <math.h>
#include <stdint.h>

#define T_LEN  2048
#define IN_DIM 1024
#define H_DIM  1024
#define FH     4096
#define C_DIM  1000
#define NCTA_DIR 64
#define SCAN_SMEM ((32*1024 + 1024) * 4)

// ---------------- device scratch (no allocations allowed) ----------------
__device__ __align__(16) float g_xp[2][T_LEN][FH];      // input projections (fwd, bwd-reversed order)
__device__ __align__(16) float g_hs[2][T_LEN][H_DIM];   // all hidden states (bwd stored in reversed time)
__device__ __align__(16) float g_hbuf[2][2][H_DIM];     // double-buffered h per direction
// per-CTA progress flags, padded to 256B so consecutive flags land on distinct LTS slices
__device__ __align__(256) unsigned g_flag[2][NCTA_DIR][64];

__device__ __forceinline__ void st_release_u32(unsigned* p, unsigned v) {
    asm volatile("st.release.gpu.global.u32 [%0],%1;" :: "l"(p), "r"(v) : "memory");
}
__device__ __forceinline__ unsigned ld_acquire_u32(const unsigned* p) {
    unsigned v;
    asm volatile("ld.acquire.gpu.global.u32 %0,[%1];" : "=r"(v) : "l"(p) : "memory");
    return v;
}

__device__ __forceinline__ float to_tf32(float x) {
    uint32_t u;
    asm("cvt.rna.tf32.f32 %0, %1;" : "=r"(u) : "f"(x));
    return __uint_as_float(u);
}

__device__ __forceinline__ void mma_tf32(float* c, const uint32_t* a, const uint32_t* b) {
    asm volatile(
        "mma.sync.aligned.m16n8k8.row.col.f32.tf32.tf32.f32 "
        "{%0,%1,%2,%3}, {%4,%5,%6,%7}, {%8,%9}, {%0,%1,%2,%3};\n"
        : "+f"(c[0]), "+f"(c[1]), "+f"(c[2]), "+f"(c[3])
        : "r"(a[0]), "r"(a[1]), "r"(a[2]), "r"(a[3]), "r"(b[0]), "r"(b[1]));
}

__device__ __forceinline__ int swz(int r, int c) {
    return r * 32 + ((((c >> 2) ^ (r & 7)) << 2) | (c & 3));
}

// ---------------- init: reset flags + h0 every launch/replay ----------------
__global__ void init_kernel() {
    int tid = blockIdx.x * blockDim.x + threadIdx.x;
    if (tid < 2 * 2 * H_DIM) ((float*)g_hbuf)[tid] = 0.f;
    if (tid < 2 * NCTA_DIR * 64) ((unsigned*)g_flag)[tid] = 1u;   // h[0] ready
}

// ---------------- phase 1: x @ W_ih^T + b_ih + b_hh via TF32 tensor cores ----------------
__global__ __launch_bounds__(256, 1) void xproj_mma(
    const float* __restrict__ x,
    const float* __restrict__ Wf, const float* __restrict__ Wb,
    const float* __restrict__ bif, const float* __restrict__ bhf,
    const float* __restrict__ bib, const float* __restrict__ bhb)
{
    const int dir = blockIdx.z;
    const float* __restrict__ W  = dir ? Wb  : Wf;
    const float* __restrict__ b1 = dir ? bib : bif;
    const float* __restrict__ b2 = dir ? bhb : bhf;

    __shared__ float sA[128 * 32];
    __shared__ float sB[128 * 32];

    const int tid = threadIdx.x;
    const int warp = tid >> 5, l = tid & 31;
    const int wm = warp >> 1, wn = warp & 1;
    const int g = l >> 2, t = l & 3;
    const int m0 = blockIdx.y * 128, n0 = blockIdx.x * 128;

    const int sr  = tid >> 3;
    const int sc4 = tid & 7;
    const int scs = ((sc4 ^ (sr & 7)) << 2);

    float acc[2][8][4];
    #pragma unroll
    for (int mi = 0; mi < 2; ++mi)
        #pragma unroll
        for (int ni = 0; ni < 8; ++ni)
            #pragma unroll
            for (int e = 0; e < 4; ++e) acc[mi][ni][e] = 0.f;

    float4 pa[4], pb[4];
    {
        const int kc = sc4 * 4;
        #pragma unroll
        for (int p = 0; p < 4; ++p) {
            int m = m0 + sr + 32 * p;
            int ar = dir ? (T_LEN - 1 - m) : m;
            pa[p] = *(const float4*)(x + (size_t)ar * IN_DIM + kc);
            pb[p] = *(const float4*)(W + (size_t)(n0 + sr + 32 * p) * IN_DIM + kc);
        }
        #pragma unroll
        for (int p = 0; p < 4; ++p) {
            int r = sr + 32 * p;
            float* da = &sA[r * 32 + scs];
            float* db = &sB[r * 32 + scs];
            da[0] = to_tf32(pa[p].x); da[1] = to_tf32(pa[p].y); da[2] = to_tf32(pa[p].z); da[3] = to_tf32(pa[p].w);
            db[0] = to_tf32(pb[p].x); db[1] = to_tf32(pb[p].y); db[2] = to_tf32(pb[p].z); db[3] = to_tf32(pb[p].w);
        }
    }
    __syncthreads();

    for (int kt = 0; kt < IN_DIM / 32; ++kt) {
        if (kt < IN_DIM / 32 - 1) {
            const int kc = (kt + 1) * 32 + sc4 * 4;
            #pragma unroll
            for (int p = 0; p < 4; ++p) {
                int m = m0 + sr + 32 * p;
                int ar = dir ? (T_LEN - 1 - m) : m;
                pa[p] = *(const float4*)(x + (size_t)ar * IN_DIM + kc);
                pb[p] = *(const float4*)(W + (size_t)(n0 + sr + 32 * p) * IN_DIM + kc);
            }
        }
        #pragma unroll
        for (int k8 = 0; k8 < 4; ++k8) {
            const int kk = k8 * 8;
            uint32_t a[2][4], b[8][2];
            #pragma unroll
            for (int mi = 0; mi < 2; ++mi) {
                int r = wm * 32 + mi * 16 + g;
                a[mi][0] = __float_as_uint(sA[swz(r,     kk + t)]);
                a[mi][1] = __float_as_uint(sA[swz(r + 8, kk + t)]);
                a[mi][2] = __float_as_uint(sA[swz(r,     kk + t + 4)]);
                a[mi][3] = __float_as_uint(sA[swz(r + 8, kk + t + 4)]);
            }
            #pragma unroll
            for (int ni = 0; ni < 8; ++ni) {
                int rn = wn * 64 + ni * 8 + g;
                b[ni][0] = __float_as_uint(sB[swz(rn, kk + t)]);
                b[ni][1] = __float_as_uint(sB[swz(rn, kk + t + 4)]);
            }
            #pragma unroll
            for (int mi = 0; mi < 2; ++mi)
                #pragma unroll
                for (int ni = 0; ni < 8; ++ni)
                    mma_tf32(acc[mi][ni], a[mi], b[ni]);
        }
        __syncthreads();
        if (kt < IN_DIM / 32 - 1) {
            #pragma unroll
            for (int p = 0; p < 4; ++p) {
                int r = sr + 32 * p;
                float* da = &sA[r * 32 + scs];
                float* db = &sB[r * 32 + scs];
                da[0] = to_tf32(pa[p].x); da[1] = to_tf32(pa[p].y); da[2] = to_tf32(pa[p].z); da[3] = to_tf32(pa[p].w);
                db[0] = to_tf32(pb[p].x); db[1] = to_tf32(pb[p].y); db[2] = to_tf32(pb[p].z); db[3] = to_tf32(pb[p].w);
            }
            __syncthreads();
        }
    }

    #pragma unroll
    for (int mi = 0; mi < 2; ++mi) {
        int r0 = m0 + wm * 32 + mi * 16 + g;
        #pragma unroll
        for (int ni = 0; ni < 8; ++ni) {
            int n = n0 + wn * 64 + ni * 8 + 2 * t;
            float bb0 = __ldg(b1 + n)     + __ldg(b2 + n);
            float bb1 = __ldg(b1 + n + 1) + __ldg(b2 + n + 1);
            float2 v0 = make_float2(acc[mi][ni][0] + bb0, acc[mi][ni][1] + bb1);
            float2 v1 = make_float2(acc[mi][ni][2] + bb0, acc[mi][ni][3] + bb1);
            *(float2*)&g_xp[dir][r0][n]     = v0;
            *(float2*)&g_xp[dir][r0 + 8][n] = v1;
        }
    }
}

// ---------------- phase 2: persistent LSTM scan, fused per-lane poll+fetch ----------------
// 128 CTAs (blockIdx>>6 = direction, &63 = chunk). 256 threads = 8 warps.
// Warp owns 2 units: unit A weights in registers, unit B in SMEM.
// Handoff: each thread polls the flag of ITS OWN producer CTA (flag[tid>>2]) and in the
// same loop iteration loads its h float4 (acquire orders the pair, so the same-iteration
// value is valid once the flag passes). No global AND, one barrier, overlapped latencies.
__global__ __launch_bounds__(256, 1) void scan_kernel(
    const float* __restrict__ Whh_f, const float* __restrict__ Whh_b)
{
    extern __shared__ float smem[];
    float* sW = smem;             // 32 rows x 1024 (unit-B weights)
    float* sH = smem + 32*1024;   // 1024 (staged h)

    const int dir = blockIdx.x >> 6;
    const int cb  = blockIdx.x & 63;
    const float* __restrict__ Whh = dir ? Whh_b : Whh_f;

    const int tid = threadIdx.x;
    const int w = tid >> 5;
    const int l = tid & 31;
    const int uA = cb*16 + w;        // register unit
    const int uB = cb*16 + 8 + w;    // smem unit

    for (int i = tid; i < 32*1024/4; i += 256) {
        int rr = i >> 8;
        int col4 = i & 255;
        int lw = rr >> 2;
        int g  = rr & 3;
        int uu = cb*16 + 8 + lw;
        ((float4*)sW)[i] = __ldg((const float4*)(Whh + (size_t)(g*H_DIM + uu)*H_DIM) + col4);
    }

    float4 wr[4][8];
    #pragma unroll
    for (int g = 0; g < 4; ++g) {
        const float4* base = (const float4*)(Whh + (size_t)(g*H_DIM + uA)*H_DIM);
        #pragma unroll
        for (int jj = 0; jj < 8; ++jj)
            wr[g][jj] = __ldg(base + (l + 32*jj));
    }
    __syncthreads();

    float cA = 0.f, cB = 0.f;
    const float* xp = &g_xp[dir][0][0];
    float* hs = &g_hs[dir][0][0];
    // lanes in a quad share one xp element: gate=(l>>2)&3, unit A for l<16 else B
    const int xrow = (((l >> 2) & 3))*H_DIM + ((l & 16) ? uB : uA);
    const unsigned* myflag = &g_flag[dir][tid >> 2][0];

    for (int step = 0; step < T_LEN; ++step) {
        // independent gmem load issued early to overlap with polling
        float xpv = __ldg(xp + (size_t)step*FH + xrow);

        // fused poll + h fetch: each thread waits on its own producer's flag and
        // re-loads its own h float4 every iteration; last iteration's value is fresh.
        const unsigned expect = (unsigned)(step + 1);
        const float4* hp = (const float4*)&g_hbuf[dir][step & 1][0] + tid;
        float4 hv;
        for (;;) {
            unsigned f = ld_acquire_u32(myflag);
            hv = __ldcg(hp);
            if (__all_sync(0xffffffffu, f >= expect)) break;
        }
        ((float4*)sH)[tid] = hv;
        __syncthreads();

        float acc[8];
        #pragma unroll
        for (int g = 0; g < 8; ++g) acc[g] = 0.f;

        const float4* sH4 = (const float4*)sH;
        const float4* sW4 = (const float4*)sW;
        #pragma unroll
        for (int jj = 0; jj < 8; ++jj) {
            float4 h4 = sH4[l + 32*jj];
            #pragma unroll
            for (int g = 0; g < 4; ++g) {
                float4 a = wr[g][jj];
                acc[g]   = fmaf(a.x,h4.x, fmaf(a.y,h4.y, fmaf(a.z,h4.z, fmaf(a.w,h4.w, acc[g]))));
                float4 b = sW4[(w*4 + g)*256 + l + 32*jj];
                acc[4+g] = fmaf(b.x,h4.x, fmaf(b.y,h4.y, fmaf(b.z,h4.z, fmaf(b.w,h4.w, acc[4+g]))));
            }
        }

        // value-merging butterfly: 16 shfls
        #pragma unroll
        for (int g = 0; g < 8; ++g) acc[g] += __shfl_xor_sync(0xffffffffu, acc[g], 16);
        float v0 = (l & 16) ? acc[4] : acc[0];
        float v1 = (l & 16) ? acc[5] : acc[1];
        float v2 = (l & 16) ? acc[6] : acc[2];
        float v3 = (l & 16) ? acc[7] : acc[3];
        v0 += __shfl_xor_sync(0xffffffffu, v0, 8);
        v1 += __shfl_xor_sync(0xffffffffu, v1, 8);
        v2 += __shfl_xor_sync(0xffffffffu, v2, 8);
        v3 += __shfl_xor_sync(0xffffffffu, v3, 8);
        float u0 = (l & 8) ? v2 : v0;
        float u1 = (l & 8) ? v3 : v1;
        u0 += __shfl_xor_sync(0xffffffffu, u0, 4);
        u1 += __shfl_xor_sync(0xffffffffu, u1, 4);
        float t = (l & 4) ? u1 : u0;
        t += __shfl_xor_sync(0xffffffffu, t, 2);
        t += __shfl_xor_sync(0xffffffffu, t, 1);
        // lane l holds gate sum for g(l) = 4*(l>>4) + ((l>>2)&3)

        float pre = t + xpv;
        float act;
        if (((l >> 2) & 3) == 2) {             // candidate gate: tanh (RCP-fast division)
            float e = __expf(-2.f * fabsf(pre));
            act = copysignf(__fdividef(1.f - e, 1.f + e), pre);
        } else {                               // i/f/o gates: sigmoid
            act = __fdividef(1.f, 1.f + __expf(-pre));
        }

        float iA = __shfl_sync(0xffffffffu, act, 0);
        float fA = __shfl_sync(0xffffffffu, act, 4);
        float gA = __shfl_sync(0xffffffffu, act, 8);
        float oA = __shfl_sync(0xffffffffu, act, 12);
        float iB = __shfl_sync(0xffffffffu, act, 16);
        float fB = __shfl_sync(0xffffffffu, act, 20);
        float gB = __shfl_sync(0xffffffffu, act, 24);
        float oB = __shfl_sync(0xffffffffu, act, 28);

        cA = fmaf(fA, cA, iA * gA);
        cB = fmaf(fB, cB, iB * gB);
        float eA = __expf(-2.f * fabsf(cA));
        float eB = __expf(-2.f * fabsf(cB));
        float hA = oA * copysignf(__fdividef(1.f - eA, 1.f + eA), cA);
        float hB = oB * copysignf(__fdividef(1.f - eB, 1.f + eB), cB);

        float* hnext = &g_hbuf[dir][(step + 1) & 1][0];
        if (l == 0) { __stcg(&hnext[uA], hA); hs[(size_t)step*H_DIM + uA] = hA; }
        if (l == 4) { __stcg(&hnext[uB], hB); hs[(size_t)step*H_DIM + uB] = hB; }
        __syncthreads();                        // all h stores issued; also protects sH reuse
        if (tid == 0) st_release_u32(&g_flag[dir][cb][0], (unsigned)(step + 2));
    }
}

// ---------------- phase 3: out = concat(h_fwd, h_bwd) @ fc_W^T + fc_b via TF32 MMA ----------------
__global__ __launch_bounds__(256, 1) void fc_mma(
    const float* __restrict__ fcW, const float* __restrict__ fcb,
    float* __restrict__ out)
{
    __shared__ float sA[128 * 32];
    __shared__ float sB[128 * 32];

    const int tid = threadIdx.x;
    const int warp = tid >> 5, l = tid & 31;
    const int wm = warp >> 1, wn = warp & 1;
    const int g = l >> 2, t = l & 3;
    const int m0 = blockIdx.y * 128, n0 = blockIdx.x * 128;

    const int sr  = tid >> 3;
    const int sc4 = tid & 7;
    const int scs = ((sc4 ^ (sr & 7)) << 2);

    float acc[2][8][4];
    #pragma unroll
    for (int mi = 0; mi < 2; ++mi)
        #pragma unroll
        for (int ni = 0; ni < 8; ++ni)
            #pragma unroll
            for (int e = 0; e < 4; ++e) acc[mi][ni][e] = 0.f;

    float4 pa[4], pb[4];
    {
        const int kc = sc4 * 4;
        #pragma unroll
        for (int p = 0; p < 4; ++p) {
            int m = m0 + sr + 32 * p;
            const float* asrc = (kc < H_DIM) ? &g_hs[0][m][kc]
                                             : &g_hs[1][T_LEN - 1 - m][kc - H_DIM];
            pa[p] = *(const float4*)asrc;
            int n = n0 + sr + 32 * p;
            pb[p] = (n < C_DIM) ? *(const float4*)(fcW + (size_t)n * (2 * H_DIM) + kc)
                                : make_float4(0.f, 0.f, 0.f, 0.f);
        }
        #pragma unroll
        for (int p = 0; p < 4; ++p) {
            int r = sr + 32 * p;
            float* da = &sA[r * 32 + scs];
            float* db = &sB[r * 32 + scs];
            da[0] = to_tf32(pa[p].x); da[1] = to_tf32(pa[p].y); da[2] = to_tf32(pa[p].z); da[3] = to_tf32(pa[p].w);
            db[0] = to_tf32(pb[p].x); db[1] = to_tf32(pb[p].y); db[2] = to_tf32(pb[p].z); db[3] = to_tf32(pb[p].w);
        }
    }
    __syncthreads();

    const int KTOT = 2 * H_DIM;
    for (int kt = 0; kt < KTOT / 32; ++kt) {
        if (kt < KTOT / 32 - 1) {
            const int kc = (kt + 1) * 32 + sc4 * 4;
            #pragma unroll
            for (int p = 0; p < 4; ++p) {
                int m = m0 + sr + 32 * p;
                const float* asrc = (kc < H_DIM) ? &g_hs[0][m][kc]
                                                 : &g_hs[1][T_LEN - 1 - m][kc - H_DIM];
                pa[p] = *(const float4*)asrc;
                int n = n0 + sr + 32 * p;
                pb[p] = (n < C_DIM) ? *(const float4*)(fcW + (size_t)n * (2 * H_DIM) + kc)
                                    : make_float4(0.f, 0.f, 0.f, 0.f);
            }
        }
        #pragma unroll
        for (int k8 = 0; k8 < 4; ++k8) {
            const int kk = k8 * 8;
            uint32_t a[2][4], b[8][2];
            #pragma unroll
            for (int mi = 0; mi < 2; ++mi) {
                int r = wm * 32 + mi * 16 + g;
                a[mi][0] = __float_as_uint(sA[swz(r,     kk + t)]);
                a[mi][1] = __float_as_uint(sA[swz(r + 8, kk + t)]);
                a[mi][2] = __float_as_uint(sA[swz(r,     kk + t + 4)]);
                a[mi][3] = __float_as_uint(sA[swz(r + 8, kk + t + 4)]);
            }
            #pragma unroll
            for (int ni = 0; ni < 8; ++ni) {
                int rn = wn * 64 + ni * 8 + g;
                b[ni][0] = __float_as_uint(sB[swz(rn, kk + t)]);
                b[ni][1] = __float_as_uint(sB[swz(rn, kk + t + 4)]);
            }
            #pragma unroll
            for (int mi = 0; mi < 2; ++mi)
                #pragma unroll
                for (int ni = 0; ni < 8; ++ni)
                    mma_tf32(acc[mi][ni], a[mi], b[ni]);
        }
        __syncthreads();
        if (kt < KTOT / 32 - 1) {
            #pragma unroll
            for (int p = 0; p < 4; ++p) {
                int r = sr + 32 * p;
                float* da = &sA[r * 32 + scs];
                float* db = &sB[r * 32 + scs];
                da[0] = to_tf32(pa[p].x); da[1] = to_tf32(pa[p].y); da[2] = to_tf32(pa[p].z); da[3] = to_tf32(pa[p].w);
                db[0] = to_tf32(pb[p].x); db[1] = to_tf32(pb[p].y); db[2] = to_tf32(pb[p].z); db[3] = to_tf32(pb[p].w);
            }
            __syncthreads();
        }
    }

    #pragma unroll
    for (int mi = 0; mi < 2; ++mi) {
        int r0 = m0 + wm * 32 + mi * 16 + g;
        #pragma unroll
        for (int ni = 0; ni < 8; ++ni) {
            int n = n0 + wn * 64 + ni * 8 + 2 * t;
            if (n < C_DIM) {
                float bb0 = __ldg(fcb + n);
                float bb1 = __ldg(fcb + n + 1);
                float2 v0 = make_float2(acc[mi][ni][0] + bb0, acc[mi][ni][1] + bb1);
                float2 v1 = make_float2(acc[mi][ni][2] + bb0, acc[mi][ni][3] + bb1);
                *(float2*)&out[(size_t)r0 * C_DIM + n]       = v0;
                *(float2*)&out[(size_t)(r0 + 8) * C_DIM + n] = v1;
            }
        }
    }
}

// ---------------- launch ----------------
extern "C" void kernel_launch(void* const* d_in, const int* in_sizes, int n_in,
                              void* d_out, int out_size)
{
    const float* x      = (const float*)d_in[0];
    const float* W_ih_f = (const float*)d_in[1];
    const float* W_hh_f = (const float*)d_in[2];
    const float* b_ih_f = (const float*)d_in[3];
    const float* b_hh_f = (const float*)d_in[4];
    const float* W_ih_b = (const float*)d_in[5];
    const float* W_hh_b = (const float*)d_in[6];
    const float* b_ih_b = (const float*)d_in[7];
    const float* b_hh_b = (const float*)d_in[8];
    const float* fc_W   = (const float*)d_in[9];
    const float* fc_b   = (const float*)d_in[10];
    float* out = (float*)d_out;

    cudaFuncSetAttribute(scan_kernel, cudaFuncAttributeMaxDynamicSharedMemorySize, SCAN_SMEM);

    init_kernel<<<32, 256>>>();
    xproj_mma<<<dim3(FH/128, T_LEN/128, 2), 256>>>(x, W_ih_f, W_ih_b,
                                                   b_ih_f, b_hh_f, b_ih_b, b_hh_b);
    scan_kernel<<<2*NCTA_DIR, 256, SCAN_SMEM>>>(W_hh_f, W_hh_b);
    fc_mma<<<dim3(8, T_LEN/128), 256>>>(fc_W, fc_b, out);
}